// round 14
// baseline (speedup 1.0000x reference)
#include <cuda_runtime.h>

// Problem constants (N=100000, E=1600000, ND=ED=OD=32)
#define NODES_MAX 100000
#define EDGES_MAX 1600000
#define SCAN_T 1024

// Device-global scratch (no allocations allowed).
__device__ int   g_count[NODES_MAX];      // in-degree
__device__ int   g_row[NODES_MAX];        // CSR row offsets
__device__ int   g_cursor[NODES_MAX];     // permutation cursors
__device__ int   g_agg[128];              // scan aggregates (+1 = ready flag)
__device__ int2  g_epair[EDGES_MAX];      // dst-sorted (src, eid)

// ---------------------------------------------------------------------------
// 1. zero histogram + scan flags
// ---------------------------------------------------------------------------
__global__ void mp_zero_kernel(int n_nodes) {
    int i = blockIdx.x * blockDim.x + threadIdx.x;
    if (i < n_nodes) g_count[i] = 0;
    if (i < 128) g_agg[i] = 0;
}

// ---------------------------------------------------------------------------
// 2. in-degree histogram
// ---------------------------------------------------------------------------
__global__ void mp_hist_kernel(const int* __restrict__ dst, int n_edges) {
    int e = blockIdx.x * blockDim.x + threadIdx.x;
    if (e < n_edges) atomicAdd(&g_count[__ldg(dst + e)], 1);
}

// ---------------------------------------------------------------------------
// 3. single-kernel exclusive scan (98 blocks, all co-resident on 148 SMs).
//    Each block scans its 1024 counts, publishes aggregate+1 via atomicExch,
//    then polls all predecessors' aggregates and sums them. Deterministic.
// ---------------------------------------------------------------------------
__global__ void __launch_bounds__(SCAN_T)
mp_scan_kernel(int n_nodes) {
    __shared__ int wsum[32];
    __shared__ int sbase;
    int t = threadIdx.x, b = blockIdx.x;
    int idx = b * SCAN_T + t;
    int v = (idx < n_nodes) ? g_count[idx] : 0;

    // warp inclusive scan
    int x = v;
#pragma unroll
    for (int o = 1; o < 32; o <<= 1) {
        int y = __shfl_up_sync(0xffffffffu, x, o);
        if ((t & 31) >= o) x += y;
    }
    if ((t & 31) == 31) wsum[t >> 5] = x;
    __syncthreads();
    if (t < 32) {
        int s = wsum[t];
#pragma unroll
        for (int o = 1; o < 32; o <<= 1) {
            int y = __shfl_up_sync(0xffffffffu, s, o);
            if (t >= o) s += y;
        }
        wsum[t] = s;
    }
    __syncthreads();
    int incl = x + ((t >= 32) ? wsum[(t >> 5) - 1] : 0);
    int total = wsum[31];

    if (t == 0) {
        sbase = 0;
        atomicExch(&g_agg[b], total + 1);   // publish: value+1 doubles as flag
    }
    __syncthreads();                         // sbase=0 visible

    if (t < b) {                             // b <= 97 predecessors
        int w;
        do { w = atomicAdd(&g_agg[t], 0); } while (w == 0);
        atomicAdd(&sbase, w - 1);
    }
    __syncthreads();

    if (idx < n_nodes) {
        int r = sbase + incl - v;            // exclusive prefix
        g_row[idx] = r;
        g_cursor[idx] = r;
    }
}

// ---------------------------------------------------------------------------
// 4. permutation: (src, eid) into dst-sorted order (int atomics only)
// ---------------------------------------------------------------------------
__global__ void mp_permute_kernel(const int* __restrict__ src,
                                  const int* __restrict__ dst,
                                  int n_edges) {
    int e = blockIdx.x * blockDim.x + threadIdx.x;
    if (e >= n_edges) return;
    int d = __ldg(dst + e);
    int pos = atomicAdd(&g_cursor[d], 1);
    g_epair[pos] = make_int2(__ldg(src + e), e);
}

// ---------------------------------------------------------------------------
// 5. FUSED gather + epilogue. Block = 256 threads = 32 nodes (4 per warp).
//    Phase 1: gather with lane=(edge_sub, f4-chunk), float4 loads -> sA.
//    Phase 2: Z = relu(S@W_pre + deg*b_pre) (deg==0 -> z_init)
//             H = relu([X|Z]@W_upd + b_upd)
// ---------------------------------------------------------------------------
__global__ void __launch_bounds__(256, 5)
mp_fused_kernel(const float4* __restrict__ node_x4,
                const float4* __restrict__ edge_x4,
                const float* __restrict__ node_x,
                const float* __restrict__ z_init,
                const float* __restrict__ W_pre,   // [64,64]
                const float* __restrict__ b_pre,   // [64]
                const float* __restrict__ W_upd,   // [96,32]
                const float* __restrict__ b_upd,   // [32]
                float* __restrict__ out,           // [N,32]
                int n_nodes) {
    __shared__ float sA[32 * 65];     // S tile, later Z tile (pitch 65)
    __shared__ float sW[64 * 64];     // W_pre, later W_upd (96*32 fits)
    __shared__ float sX[32 * 33];     // node_x tile
    __shared__ float sbp[64];
    __shared__ float sbu[32];
    __shared__ float sdeg[32];        // degree as float (GEMM1 bias)
    __shared__ int   srow[32];        // CSR start
    __shared__ int   scnt[32];        // degree as int (gather)

    int t = threadIdx.x;
    int nb0 = blockIdx.x * 32;
    int nvalid = n_nodes - nb0;
    if (nvalid > 32) nvalid = 32;

    // ---- stage weights / X / biases / row info ----
    for (int idx = t; idx < 64 * 64; idx += 256) sW[idx] = W_pre[idx];
    for (int idx = t; idx < 32 * 32; idx += 256) {
        int r = idx >> 5, c = idx & 31;
        sX[r * 33 + c] = (r < nvalid) ? node_x[(size_t)(nb0 + r) * 32 + c] : 0.f;
    }
    if (t < 64) sbp[t] = b_pre[t];
    if (t < 32) {
        sbu[t] = b_upd[t];
        int cnt = (t < nvalid) ? g_count[nb0 + t] : 0;
        scnt[t] = cnt;
        sdeg[t] = (float)cnt;
        srow[t] = (t < nvalid) ? g_row[nb0 + t] : 0;
    }
    __syncthreads();

    // ---- phase 1: gather. warp w handles local nodes w*4 .. w*4+3 ----
    {
        int w = t >> 5, lane = t & 31;
        int sub = lane >> 3;          // edge slot within 4-group
        int f4  = lane & 7;           // float4 chunk of the 32-float row
#pragma unroll
        for (int i = 0; i < 4; i++) {
            int ln = w * 4 + i;
            float4 s0 = make_float4(0.f, 0.f, 0.f, 0.f);
            float4 s1 = make_float4(0.f, 0.f, 0.f, 0.f);
            if (ln < nvalid) {                       // warp-uniform
                int start = srow[ln];
                int end   = start + scnt[ln];
                for (int base = start; base < end; base += 8) {
                    int i0 = base + sub;
                    int i1 = i0 + 4;
                    if (i0 < end) {
                        int2 p = g_epair[i0];
                        float4 nv = __ldg(node_x4 + (size_t)p.x * 8 + f4);
                        float4 ev = __ldg(edge_x4 + (size_t)p.y * 8 + f4);
                        s0.x += nv.x; s0.y += nv.y; s0.z += nv.z; s0.w += nv.w;
                        s1.x += ev.x; s1.y += ev.y; s1.z += ev.z; s1.w += ev.w;
                    }
                    if (i1 < end) {
                        int2 p = g_epair[i1];
                        float4 nv = __ldg(node_x4 + (size_t)p.x * 8 + f4);
                        float4 ev = __ldg(edge_x4 + (size_t)p.y * 8 + f4);
                        s0.x += nv.x; s0.y += nv.y; s0.z += nv.z; s0.w += nv.w;
                        s1.x += ev.x; s1.y += ev.y; s1.z += ev.z; s1.w += ev.w;
                    }
                }
            }
            // reduce over sub (lane bits 3,4)
#pragma unroll
            for (int off = 8; off <= 16; off <<= 1) {
                s0.x += __shfl_xor_sync(0xffffffffu, s0.x, off);
                s0.y += __shfl_xor_sync(0xffffffffu, s0.y, off);
                s0.z += __shfl_xor_sync(0xffffffffu, s0.z, off);
                s0.w += __shfl_xor_sync(0xffffffffu, s0.w, off);
                s1.x += __shfl_xor_sync(0xffffffffu, s1.x, off);
                s1.y += __shfl_xor_sync(0xffffffffu, s1.y, off);
                s1.z += __shfl_xor_sync(0xffffffffu, s1.z, off);
                s1.w += __shfl_xor_sync(0xffffffffu, s1.w, off);
            }
            if (sub == 0) {
                float* d = &sA[ln * 65 + f4 * 4];
                d[0] = s0.x; d[1] = s0.y; d[2] = s0.z; d[3] = s0.w;
            } else if (sub == 1) {
                float* d = &sA[ln * 65 + 32 + f4 * 4];
                d[0] = s1.x; d[1] = s1.y; d[2] = s1.z; d[3] = s1.w;
            }
        }
    }
    __syncthreads();

    // ---- GEMM1: 32x64 output, 2x4 micro-tile per thread ----
    float acc[2][4];
    {
        int tx = t & 15, ty = t >> 4;     // tx: col group, ty: 0..15 row pair
        int c0 = tx * 4, r0 = ty * 2;
#pragma unroll
        for (int r = 0; r < 2; r++)
#pragma unroll
            for (int c = 0; c < 4; c++) acc[r][c] = sdeg[r0 + r] * sbp[c0 + c];

#pragma unroll 8
        for (int k = 0; k < 64; k++) {
            float a0 = sA[(r0 + 0) * 65 + k];
            float a1 = sA[(r0 + 1) * 65 + k];
            float4 bv = *(const float4*)&sW[k * 64 + c0];
#pragma unroll
            for (int c = 0; c < 4; c++) {
                float b = (c == 0) ? bv.x : (c == 1) ? bv.y : (c == 2) ? bv.z : bv.w;
                acc[0][c] = fmaf(a0, b, acc[0][c]);
                acc[1][c] = fmaf(a1, b, acc[1][c]);
            }
        }
    }
    __syncthreads();     // all reads of sA (S) and sW (W_pre) done

    // ---- write Z into sA; reload sW with W_upd ----
    {
        int tx = t & 15, ty = t >> 4;
        int c0 = tx * 4, r0 = ty * 2;
#pragma unroll
        for (int r = 0; r < 2; r++)
#pragma unroll
            for (int c = 0; c < 4; c++)
                sA[(r0 + r) * 65 + c0 + c] = fmaxf(acc[r][c], 0.f);
    }
    for (int idx = t; idx < 96 * 32; idx += 256) sW[idx] = W_upd[idx];
    __syncthreads();

    // ---- deg==0 rows take z_init (rare) ----
    if (t < nvalid && scnt[t] == 0) {
        for (int c = 0; c < 64; c++)
            sA[t * 65 + c] = z_init[(size_t)(nb0 + t) * 64 + c];
    }
    __syncthreads();

    // ---- GEMM2: 32x32 output, 1x4 micro-tile per thread ----
    {
        int tx = t & 7, r0 = t >> 3;      // r0: 0..31
        int c0 = tx * 4;
        float h[4];
#pragma unroll
        for (int c = 0; c < 4; c++) h[c] = sbu[c0 + c];

#pragma unroll 8
        for (int k = 0; k < 32; k++) {       // node_x part (rows 0..31)
            float a = sX[r0 * 33 + k];
            float4 bv = *(const float4*)&sW[k * 32 + c0];
            h[0] = fmaf(a, bv.x, h[0]);
            h[1] = fmaf(a, bv.y, h[1]);
            h[2] = fmaf(a, bv.z, h[2]);
            h[3] = fmaf(a, bv.w, h[3]);
        }
#pragma unroll 8
        for (int k = 0; k < 64; k++) {       // z part (rows 32..95)
            float a = sA[r0 * 65 + k];
            float4 bv = *(const float4*)&sW[(32 + k) * 32 + c0];
            h[0] = fmaf(a, bv.x, h[0]);
            h[1] = fmaf(a, bv.y, h[1]);
            h[2] = fmaf(a, bv.z, h[2]);
            h[3] = fmaf(a, bv.w, h[3]);
        }
        if (r0 < nvalid) {
#pragma unroll
            for (int c = 0; c < 4; c++)
                out[(size_t)(nb0 + r0) * 32 + c0 + c] = fmaxf(h[c], 0.f);
        }
    }
}

// ---------------------------------------------------------------------------
// Launch. Inputs: node_x, edge_x, z_init, W_pre, b_pre, W_upd, b_upd, src, dst
// ---------------------------------------------------------------------------
extern "C" void kernel_launch(void* const* d_in, const int* in_sizes, int n_in,
                              void* d_out, int out_size) {
    const float* node_x = (const float*)d_in[0];
    const float* edge_x = (const float*)d_in[1];
    const float* z_init = (const float*)d_in[2];
    const float* W_pre  = (const float*)d_in[3];
    const float* b_pre  = (const float*)d_in[4];
    const float* W_upd  = (const float*)d_in[5];
    const float* b_upd  = (const float*)d_in[6];
    const int*   src    = (const int*)d_in[7];
    const int*   dst    = (const int*)d_in[8];
    float* out = (float*)d_out;

    int n_nodes = in_sizes[0] / 32;   // 100000
    int n_edges = in_sizes[7];        // 1600000
    int nb = (n_nodes + SCAN_T - 1) / SCAN_T;   // 98 (all co-resident)

    mp_zero_kernel<<<(n_nodes + 255) / 256, 256>>>(n_nodes);
    mp_hist_kernel<<<(n_edges + 255) / 256, 256>>>(dst, n_edges);
    mp_scan_kernel<<<nb, SCAN_T>>>(n_nodes);
    mp_permute_kernel<<<(n_edges + 255) / 256, 256>>>(src, dst, n_edges);
    mp_fused_kernel<<<(n_nodes + 31) / 32, 256>>>(
        (const float4*)node_x, (const float4*)edge_x,
        node_x, z_init, W_pre, b_pre, W_upd, b_upd, out, n_nodes);
}

// round 15
// speedup vs baseline: 1.0015x; 1.0015x over previous
#include <cuda_runtime.h>

// Problem constants (N=100000, E=1600000, ND=ED=OD=32)
#define NODES_MAX 100000
#define EDGES_MAX 1600000
#define SCAN_T 1024

// Device-global scratch (no allocations allowed).
__device__ int   g_count[NODES_MAX];      // in-degree
__device__ int   g_row[NODES_MAX];        // CSR row offsets
__device__ int   g_cursor[NODES_MAX];     // permutation cursors
__device__ int   g_agg[128];              // scan aggregates (+1 = ready flag)
__device__ int2  g_epair[EDGES_MAX];      // dst-sorted (src, eid)

// ---------------------------------------------------------------------------
// 1. zero histogram + scan flags
// ---------------------------------------------------------------------------
__global__ void mp_zero_kernel(int n_nodes) {
    int i = blockIdx.x * blockDim.x + threadIdx.x;
    if (i < n_nodes) g_count[i] = 0;
    if (i < 128) g_agg[i] = 0;
}

// ---------------------------------------------------------------------------
// 2. in-degree histogram
// ---------------------------------------------------------------------------
__global__ void mp_hist_kernel(const int* __restrict__ dst, int n_edges) {
    int e = blockIdx.x * blockDim.x + threadIdx.x;
    if (e < n_edges) atomicAdd(&g_count[__ldg(dst + e)], 1);
}

// ---------------------------------------------------------------------------
// 3. single-kernel exclusive scan (98 blocks, all co-resident on 148 SMs).
//    Each block scans its 1024 counts, publishes aggregate+1 via atomicExch,
//    then polls all predecessors' aggregates and sums them. Deterministic.
// ---------------------------------------------------------------------------
__global__ void __launch_bounds__(SCAN_T)
mp_scan_kernel(int n_nodes) {
    __shared__ int wsum[32];
    __shared__ int sbase;
    int t = threadIdx.x, b = blockIdx.x;
    int idx = b * SCAN_T + t;
    int v = (idx < n_nodes) ? g_count[idx] : 0;

    // warp inclusive scan
    int x = v;
#pragma unroll
    for (int o = 1; o < 32; o <<= 1) {
        int y = __shfl_up_sync(0xffffffffu, x, o);
        if ((t & 31) >= o) x += y;
    }
    if ((t & 31) == 31) wsum[t >> 5] = x;
    __syncthreads();
    if (t < 32) {
        int s = wsum[t];
#pragma unroll
        for (int o = 1; o < 32; o <<= 1) {
            int y = __shfl_up_sync(0xffffffffu, s, o);
            if (t >= o) s += y;
        }
        wsum[t] = s;
    }
    __syncthreads();
    int incl = x + ((t >= 32) ? wsum[(t >> 5) - 1] : 0);
    int total = wsum[31];

    if (t == 0) {
        sbase = 0;
        atomicExch(&g_agg[b], total + 1);   // publish: value+1 doubles as flag
    }
    __syncthreads();                         // sbase=0 visible

    if (t < b) {                             // b <= 97 predecessors
        int w;
        do { w = atomicAdd(&g_agg[t], 0); } while (w == 0);
        atomicAdd(&sbase, w - 1);
    }
    __syncthreads();

    if (idx < n_nodes) {
        int r = sbase + incl - v;            // exclusive prefix
        g_row[idx] = r;
        g_cursor[idx] = r;
    }
}

// ---------------------------------------------------------------------------
// 4. permutation: (src, eid) into dst-sorted order (int atomics only)
// ---------------------------------------------------------------------------
__global__ void mp_permute_kernel(const int* __restrict__ src,
                                  const int* __restrict__ dst,
                                  int n_edges) {
    int e = blockIdx.x * blockDim.x + threadIdx.x;
    if (e >= n_edges) return;
    int d = __ldg(dst + e);
    int pos = atomicAdd(&g_cursor[d], 1);
    g_epair[pos] = make_int2(__ldg(src + e), e);
}

// ---------------------------------------------------------------------------
// 5. FUSED gather + epilogue. Block = 256 threads = 32 nodes (4 per warp).
//    Phase 1: gather with lane=(edge_sub, f4-chunk), float4 loads -> sA.
//    Phase 2: Z = relu(S@W_pre + deg*b_pre) (deg==0 -> z_init)
//             H = relu([X|Z]@W_upd + b_upd)
// ---------------------------------------------------------------------------
__global__ void __launch_bounds__(256, 5)
mp_fused_kernel(const float4* __restrict__ node_x4,
                const float4* __restrict__ edge_x4,
                const float* __restrict__ node_x,
                const float* __restrict__ z_init,
                const float* __restrict__ W_pre,   // [64,64]
                const float* __restrict__ b_pre,   // [64]
                const float* __restrict__ W_upd,   // [96,32]
                const float* __restrict__ b_upd,   // [32]
                float* __restrict__ out,           // [N,32]
                int n_nodes) {
    __shared__ float sA[32 * 65];     // S tile, later Z tile (pitch 65)
    __shared__ float sW[64 * 64];     // W_pre, later W_upd (96*32 fits)
    __shared__ float sX[32 * 33];     // node_x tile
    __shared__ float sbp[64];
    __shared__ float sbu[32];
    __shared__ float sdeg[32];        // degree as float (GEMM1 bias)
    __shared__ int   srow[32];        // CSR start
    __shared__ int   scnt[32];        // degree as int (gather)

    int t = threadIdx.x;
    int nb0 = blockIdx.x * 32;
    int nvalid = n_nodes - nb0;
    if (nvalid > 32) nvalid = 32;

    // ---- stage weights / X / biases / row info ----
    for (int idx = t; idx < 64 * 64; idx += 256) sW[idx] = W_pre[idx];
    for (int idx = t; idx < 32 * 32; idx += 256) {
        int r = idx >> 5, c = idx & 31;
        sX[r * 33 + c] = (r < nvalid) ? node_x[(size_t)(nb0 + r) * 32 + c] : 0.f;
    }
    if (t < 64) sbp[t] = b_pre[t];
    if (t < 32) {
        sbu[t] = b_upd[t];
        int cnt = (t < nvalid) ? g_count[nb0 + t] : 0;
        scnt[t] = cnt;
        sdeg[t] = (float)cnt;
        srow[t] = (t < nvalid) ? g_row[nb0 + t] : 0;
    }
    __syncthreads();

    // ---- phase 1: gather. warp w handles local nodes w*4 .. w*4+3 ----
    {
        int w = t >> 5, lane = t & 31;
        int sub = lane >> 3;          // edge slot within 4-group
        int f4  = lane & 7;           // float4 chunk of the 32-float row
#pragma unroll
        for (int i = 0; i < 4; i++) {
            int ln = w * 4 + i;
            float4 s0 = make_float4(0.f, 0.f, 0.f, 0.f);
            float4 s1 = make_float4(0.f, 0.f, 0.f, 0.f);
            if (ln < nvalid) {                       // warp-uniform
                int start = srow[ln];
                int end   = start + scnt[ln];
                for (int base = start; base < end; base += 8) {
                    int i0 = base + sub;
                    int i1 = i0 + 4;
                    if (i0 < end) {
                        int2 p = g_epair[i0];
                        float4 nv = __ldg(node_x4 + (size_t)p.x * 8 + f4);
                        float4 ev = __ldg(edge_x4 + (size_t)p.y * 8 + f4);
                        s0.x += nv.x; s0.y += nv.y; s0.z += nv.z; s0.w += nv.w;
                        s1.x += ev.x; s1.y += ev.y; s1.z += ev.z; s1.w += ev.w;
                    }
                    if (i1 < end) {
                        int2 p = g_epair[i1];
                        float4 nv = __ldg(node_x4 + (size_t)p.x * 8 + f4);
                        float4 ev = __ldg(edge_x4 + (size_t)p.y * 8 + f4);
                        s0.x += nv.x; s0.y += nv.y; s0.z += nv.z; s0.w += nv.w;
                        s1.x += ev.x; s1.y += ev.y; s1.z += ev.z; s1.w += ev.w;
                    }
                }
            }
            // reduce over sub (lane bits 3,4)
#pragma unroll
            for (int off = 8; off <= 16; off <<= 1) {
                s0.x += __shfl_xor_sync(0xffffffffu, s0.x, off);
                s0.y += __shfl_xor_sync(0xffffffffu, s0.y, off);
                s0.z += __shfl_xor_sync(0xffffffffu, s0.z, off);
                s0.w += __shfl_xor_sync(0xffffffffu, s0.w, off);
                s1.x += __shfl_xor_sync(0xffffffffu, s1.x, off);
                s1.y += __shfl_xor_sync(0xffffffffu, s1.y, off);
                s1.z += __shfl_xor_sync(0xffffffffu, s1.z, off);
                s1.w += __shfl_xor_sync(0xffffffffu, s1.w, off);
            }
            if (sub == 0) {
                float* d = &sA[ln * 65 + f4 * 4];
                d[0] = s0.x; d[1] = s0.y; d[2] = s0.z; d[3] = s0.w;
            } else if (sub == 1) {
                float* d = &sA[ln * 65 + 32 + f4 * 4];
                d[0] = s1.x; d[1] = s1.y; d[2] = s1.z; d[3] = s1.w;
            }
        }
    }
    __syncthreads();

    // ---- GEMM1: 32x64 output, 2x4 micro-tile per thread ----
    float acc[2][4];
    {
        int tx = t & 15, ty = t >> 4;     // tx: col group, ty: 0..15 row pair
        int c0 = tx * 4, r0 = ty * 2;
#pragma unroll
        for (int r = 0; r < 2; r++)
#pragma unroll
            for (int c = 0; c < 4; c++) acc[r][c] = sdeg[r0 + r] * sbp[c0 + c];

#pragma unroll 8
        for (int k = 0; k < 64; k++) {
            float a0 = sA[(r0 + 0) * 65 + k];
            float a1 = sA[(r0 + 1) * 65 + k];
            float4 bv = *(const float4*)&sW[k * 64 + c0];
#pragma unroll
            for (int c = 0; c < 4; c++) {
                float b = (c == 0) ? bv.x : (c == 1) ? bv.y : (c == 2) ? bv.z : bv.w;
                acc[0][c] = fmaf(a0, b, acc[0][c]);
                acc[1][c] = fmaf(a1, b, acc[1][c]);
            }
        }
    }
    __syncthreads();     // all reads of sA (S) and sW (W_pre) done

    // ---- write Z into sA; reload sW with W_upd ----
    {
        int tx = t & 15, ty = t >> 4;
        int c0 = tx * 4, r0 = ty * 2;
#pragma unroll
        for (int r = 0; r < 2; r++)
#pragma unroll
            for (int c = 0; c < 4; c++)
                sA[(r0 + r) * 65 + c0 + c] = fmaxf(acc[r][c], 0.f);
    }
    for (int idx = t; idx < 96 * 32; idx += 256) sW[idx] = W_upd[idx];
    __syncthreads();

    // ---- deg==0 rows take z_init (rare) ----
    if (t < nvalid && scnt[t] == 0) {
        for (int c = 0; c < 64; c++)
            sA[t * 65 + c] = z_init[(size_t)(nb0 + t) * 64 + c];
    }
    __syncthreads();

    // ---- GEMM2: 32x32 output, 1x4 micro-tile per thread ----
    {
        int tx = t & 7, r0 = t >> 3;      // r0: 0..31
        int c0 = tx * 4;
        float h[4];
#pragma unroll
        for (int c = 0; c < 4; c++) h[c] = sbu[c0 + c];

#pragma unroll 8
        for (int k = 0; k < 32; k++) {       // node_x part (rows 0..31)
            float a = sX[r0 * 33 + k];
            float4 bv = *(const float4*)&sW[k * 32 + c0];
            h[0] = fmaf(a, bv.x, h[0]);
            h[1] = fmaf(a, bv.y, h[1]);
            h[2] = fmaf(a, bv.z, h[2]);
            h[3] = fmaf(a, bv.w, h[3]);
        }
#pragma unroll 8
        for (int k = 0; k < 64; k++) {       // z part (rows 32..95)
            float a = sA[r0 * 65 + k];
            float4 bv = *(const float4*)&sW[(32 + k) * 32 + c0];
            h[0] = fmaf(a, bv.x, h[0]);
            h[1] = fmaf(a, bv.y, h[1]);
            h[2] = fmaf(a, bv.z, h[2]);
            h[3] = fmaf(a, bv.w, h[3]);
        }
        if (r0 < nvalid) {
#pragma unroll
            for (int c = 0; c < 4; c++)
                out[(size_t)(nb0 + r0) * 32 + c0 + c] = fmaxf(h[c], 0.f);
        }
    }
}

// ---------------------------------------------------------------------------
// Launch. Inputs: node_x, edge_x, z_init, W_pre, b_pre, W_upd, b_upd, src, dst
// ---------------------------------------------------------------------------
extern "C" void kernel_launch(void* const* d_in, const int* in_sizes, int n_in,
                              void* d_out, int out_size) {
    const float* node_x = (const float*)d_in[0];
    const float* edge_x = (const float*)d_in[1];
    const float* z_init = (const float*)d_in[2];
    const float* W_pre  = (const float*)d_in[3];
    const float* b_pre  = (const float*)d_in[4];
    const float* W_upd  = (const float*)d_in[5];
    const float* b_upd  = (const float*)d_in[6];
    const int*   src    = (const int*)d_in[7];
    const int*   dst    = (const int*)d_in[8];
    float* out = (float*)d_out;

    int n_nodes = in_sizes[0] / 32;   // 100000
    int n_edges = in_sizes[7];        // 1600000
    int nb = (n_nodes + SCAN_T - 1) / SCAN_T;   // 98 (all co-resident)

    mp_zero_kernel<<<(n_nodes + 255) / 256, 256>>>(n_nodes);
    mp_hist_kernel<<<(n_edges + 255) / 256, 256>>>(dst, n_edges);
    mp_scan_kernel<<<nb, SCAN_T>>>(n_nodes);
    mp_permute_kernel<<<(n_edges + 255) / 256, 256>>>(src, dst, n_edges);
    mp_fused_kernel<<<(n_nodes + 31) / 32, 256>>>(
        (const float4*)node_x, (const float4*)edge_x,
        node_x, z_init, W_pre, b_pre, W_upd, b_upd, out, n_nodes);
}